// round 4
// baseline (speedup 1.0000x reference)
#include <cuda_runtime.h>
#include <cuda_bf16.h>
#include <math.h>

// Problem constants
#define BB   2
#define SS   2048
#define DD   128
#define NN   2048
#define MM   (BB * SS)          // 4096 rows
#define NCH  32                 // scan chunks
#define LCH  64                 // steps per chunk (NCH*LCH == SS)

// ---------------- scratch (static device globals; no allocations) ----------------
__device__ __nv_bfloat16 g_xh[MM * DD], g_xl[MM * DD];           // split x
__device__ __nv_bfloat16 g_Wh[3 * NN * DD], g_Wl[3 * NN * DD];   // split [W_B; W_C; W_dt]
__device__ __nv_bfloat16 g_Woh[DD * NN], g_Wol[DD * NN];         // split W_out
__device__ float g_abar[MM * NN];                                // exp(dt*A)
__device__ float g_bbar[MM * NN];                                // dt*B_feat
__device__ float g_cf  [MM * NN];                                // C_feat
__device__ __nv_bfloat16 g_yh[MM * NN], g_yl[MM * NN];           // split y = c*h
__device__ float g_Aprod [BB * NCH * NN];
__device__ float g_Hend  [BB * NCH * NN];
__device__ float g_Hstart[BB * NCH * NN];
__device__ float g_part[4 * MM * DD];                            // split-K partials

// ---------------- helpers ----------------
__device__ __forceinline__ void bf16_split(float v, __nv_bfloat16& h, __nv_bfloat16& l) {
    h = __float2bfloat16(v);
    l = __float2bfloat16(v - __bfloat162float(h));
}

__device__ __forceinline__ void mma_bf16(float* c, const unsigned* a, const unsigned* b) {
    asm volatile(
        "mma.sync.aligned.m16n8k16.row.col.f32.bf16.bf16.f32 "
        "{%0,%1,%2,%3}, {%4,%5,%6,%7}, {%8,%9}, {%0,%1,%2,%3};\n"
        : "+f"(c[0]), "+f"(c[1]), "+f"(c[2]), "+f"(c[3])
        : "r"(a[0]), "r"(a[1]), "r"(a[2]), "r"(a[3]),
          "r"(b[0]), "r"(b[1]));
}

// ---------------- 0) split inputs into bf16 hi/lo ----------------
__global__ void split_kernel(const float* __restrict__ x,
                             const float* __restrict__ WB,
                             const float* __restrict__ WC,
                             const float* __restrict__ Wdt,
                             const float* __restrict__ Wout) {
    const int XE  = MM * DD;        // 524288
    const int WE  = NN * DD;        // 262144 per matrix
    const int WOE = DD * NN;        // 262144
    int i = blockIdx.x * blockDim.x + threadIdx.x;
    if (i < XE) {
        bf16_split(x[i], g_xh[i], g_xl[i]);
    } else if (i < XE + 3 * WE) {
        int j = i - XE;
        const float* W = (j < WE) ? WB : ((j < 2 * WE) ? WC : Wdt);
        float v = W[j % WE];
        bf16_split(v, g_Wh[j], g_Wl[j]);
    } else if (i < XE + 3 * WE + WOE) {
        int j = i - XE - 3 * WE;
        bf16_split(Wout[j], g_Woh[j], g_Wol[j]);
    }
}

// ---------------- 1) fused projection GEMM + SSM featurizer epilogue ----------------
// Computes, for all (m, n): dot(x[m,:], W_mat[n,:]) for the three matrices,
// then abar = exp(softplus(dt)*(-exp(A_log))), bbar = softplus(dt)*B_feat, cf = C_feat.
// Block tile: 128 (m) x 64 (n), full K=128 in 4 chunks of 32. 8 warps (4x2).
__global__ __launch_bounds__(256, 1)
void gemm1_proj(const float* __restrict__ bB, const float* __restrict__ bC,
                const float* __restrict__ bdt, const float* __restrict__ Alog) {
    __shared__ unsigned short sX[2][128][36];       // [hi/lo][row][k], padded pitch 36
    __shared__ unsigned short sW[3][2][64][36];     // [mat][hi/lo][row][k]

    const int tid  = threadIdx.x;
    const int warp = tid >> 5, lane = tid & 31;
    const int wm = warp >> 1, wn = warp & 1;
    const int m0 = blockIdx.y * 128;
    const int n0 = blockIdx.x * 64;
    const int g  = lane >> 2, tg = lane & 3;

    float acc[3][2][4][4];
    #pragma unroll
    for (int a = 0; a < 3; a++)
        #pragma unroll
        for (int b = 0; b < 2; b++)
            #pragma unroll
            for (int c = 0; c < 4; c++)
                #pragma unroll
                for (int d = 0; d < 4; d++) acc[a][b][c][d] = 0.f;

    for (int kc = 0; kc < 4; kc++) {
        // load x tile (hi+lo): 2*128*16 = 4096 words
        for (int i = tid; i < 4096; i += 256) {
            int sel = i >> 11, r = (i >> 4) & 127, w = i & 15;
            const unsigned* src = (const unsigned*)((sel ? g_xl : g_xh) + (m0 + r) * DD + kc * 32);
            *(unsigned*)&sX[sel][r][w * 2] = src[w];
        }
        // load W tiles: 3*2*64*16 = 6144 words
        for (int i = tid; i < 6144; i += 256) {
            int mat = i >> 11, sel = (i >> 10) & 1, r = (i >> 4) & 63, w = i & 15;
            const unsigned* src = (const unsigned*)((sel ? g_Wl : g_Wh) + (mat * NN + n0 + r) * DD + kc * 32);
            *(unsigned*)&sW[mat][sel][r][w * 2] = src[w];
        }
        __syncthreads();

        #pragma unroll
        for (int ks = 0; ks < 2; ks++) {
            const int kb = ks * 16;
            #pragma unroll
            for (int pass = 0; pass < 3; pass++) {
                const int as = pass >> 1;   // 0,0,1
                const int bs = pass & 1;    // 0,1,0
                unsigned afr[2][4];
                #pragma unroll
                for (int mt = 0; mt < 2; mt++) {
                    int row = wm * 32 + mt * 16 + g;
                    #pragma unroll
                    for (int rg = 0; rg < 4; rg++) {
                        int r2 = row + (rg & 1) * 8;
                        int c  = kb + tg * 2 + (rg >> 1) * 8;
                        afr[mt][rg] = *(const unsigned*)&sX[as][r2][c];
                    }
                }
                #pragma unroll
                for (int nt = 0; nt < 4; nt++) {
                    int nn = wn * 32 + nt * 8 + g;
                    #pragma unroll
                    for (int mat = 0; mat < 3; mat++) {
                        unsigned bfr[2];
                        #pragma unroll
                        for (int rg = 0; rg < 2; rg++) {
                            int k = kb + tg * 2 + rg * 8;
                            bfr[rg] = *(const unsigned*)&sW[mat][bs][nn][k];
                        }
                        #pragma unroll
                        for (int mt = 0; mt < 2; mt++)
                            mma_bf16(acc[mat][mt][nt], afr[mt], bfr);
                    }
                }
            }
        }
        __syncthreads();
    }

    // epilogue: SSM featurizer transforms, vectorized float2 stores
    #pragma unroll
    for (int mt = 0; mt < 2; mt++) {
        #pragma unroll
        for (int nt = 0; nt < 4; nt++) {
            int mrow0 = m0 + wm * 32 + mt * 16 + g;
            int ncol0 = n0 + wn * 32 + nt * 8 + tg * 2;
            #pragma unroll
            for (int half = 0; half < 2; half++) {    // half: 0 -> rows g, 1 -> rows g+8
                int mr = mrow0 + half * 8;
                float2 oab, obb, ocf;
                #pragma unroll
                for (int col = 0; col < 2; col++) {
                    int rg = half * 2 + col;
                    int nc = ncol0 + col;
                    float vB = acc[0][mt][nt][rg] + bB[nc];
                    float vC = acc[1][mt][nt][rg] + bC[nc];
                    float t  = acc[2][mt][nt][rg] + bdt[nc];
                    float dtv = (t > 20.f) ? t : log1pf(__expf(t));
                    float A = -__expf(Alog[nc]);
                    float ab = __expf(dtv * A);
                    ((float*)&oab)[col] = ab;
                    ((float*)&obb)[col] = dtv * vB;
                    ((float*)&ocf)[col] = vC;
                }
                int idx = mr * NN + ncol0;
                *(float2*)&g_abar[idx] = oab;
                *(float2*)&g_bbar[idx] = obb;
                *(float2*)&g_cf[idx]   = ocf;
            }
        }
    }
}

// ---------------- 2) chunked scan pass 1: per-chunk (prod a, local h) ----------------
__global__ void scan_pass1() {
    int t  = blockIdx.x * blockDim.x + threadIdx.x;   // 131072 threads
    int n  = t & (NN - 1);
    int ch = (t >> 11) & (NCH - 1);
    int b  = t >> 16;
    const float* pa = g_abar + (b * SS + ch * LCH) * NN + n;
    const float* pb = g_bbar + (b * SS + ch * LCH) * NN + n;
    float h = 0.f, p = 1.f;
    #pragma unroll 8
    for (int s = 0; s < LCH; s++) {
        float a = pa[s * NN];
        float bb = pb[s * NN];
        h = fmaf(a, h, bb);
        p *= a;
    }
    int o = (b * NCH + ch) * NN + n;
    g_Aprod[o] = p;
    g_Hend[o]  = h;
}

// ---------------- 3) serial combine over chunks (tiny) ----------------
__global__ void scan_combine() {
    int t = blockIdx.x * blockDim.x + threadIdx.x;    // 4096 threads
    int n = t & (NN - 1);
    int b = t >> 11;
    float cur = 0.f;
    #pragma unroll
    for (int ch = 0; ch < NCH; ch++) {
        int i = (b * NCH + ch) * NN + n;
        g_Hstart[i] = cur;
        cur = fmaf(g_Aprod[i], cur, g_Hend[i]);
    }
}

// ---------------- 4) scan pass 2: replay with correct h0, emit y split ----------------
__global__ void scan_pass2() {
    int t  = blockIdx.x * blockDim.x + threadIdx.x;
    int n  = t & (NN - 1);
    int ch = (t >> 11) & (NCH - 1);
    int b  = t >> 16;
    int base = (b * SS + ch * LCH) * NN + n;
    const float* pa = g_abar + base;
    const float* pb = g_bbar + base;
    const float* pc = g_cf   + base;
    __nv_bfloat16* yh = g_yh + base;
    __nv_bfloat16* yl = g_yl + base;
    float h = g_Hstart[(b * NCH + ch) * NN + n];
    #pragma unroll 8
    for (int s = 0; s < LCH; s++) {
        float a = pa[s * NN];
        float bb = pb[s * NN];
        h = fmaf(a, h, bb);
        float y = pc[s * NN] * h;
        __nv_bfloat16 hi, lo;
        bf16_split(y, hi, lo);
        yh[s * NN] = hi;
        yl[s * NN] = lo;
    }
}

// ---------------- 5) output projection GEMM (split-K=4, deterministic partials) ----
// out[m,d] = sum_n y[m,n] * W_out[d,n].  Block: 64 (m) x 128 (d), K chunk 512 per block.
__global__ __launch_bounds__(256, 1)
void gemm2_out() {
    __shared__ unsigned short sY[2][64][36];
    __shared__ unsigned short sWo[2][128][36];

    const int tid  = threadIdx.x;
    const int warp = tid >> 5, lane = tid & 31;
    const int wm = warp >> 2, wn = warp & 3;
    const int m0 = blockIdx.x * 64;
    const int kp = blockIdx.y;              // 0..3
    const int g  = lane >> 2, tg = lane & 3;

    float acc[2][4][4];
    #pragma unroll
    for (int a = 0; a < 2; a++)
        #pragma unroll
        for (int b = 0; b < 4; b++)
            #pragma unroll
            for (int c = 0; c < 4; c++) acc[a][b][c] = 0.f;

    for (int kc = 0; kc < 16; kc++) {
        const int kbase = kp * 512 + kc * 32;
        for (int i = tid; i < 2048; i += 256) {   // y tile
            int sel = i >> 10, r = (i >> 4) & 63, w = i & 15;
            const unsigned* src = (const unsigned*)((sel ? g_yl : g_yh) + (m0 + r) * NN + kbase);
            *(unsigned*)&sY[sel][r][w * 2] = src[w];
        }
        for (int i = tid; i < 4096; i += 256) {   // W_out tile
            int sel = i >> 11, r = (i >> 4) & 127, w = i & 15;
            const unsigned* src = (const unsigned*)((sel ? g_Wol : g_Woh) + r * NN + kbase);
            *(unsigned*)&sWo[sel][r][w * 2] = src[w];
        }
        __syncthreads();

        #pragma unroll
        for (int ks = 0; ks < 2; ks++) {
            const int kb = ks * 16;
            #pragma unroll
            for (int pass = 0; pass < 3; pass++) {
                const int as = pass >> 1;
                const int bs = pass & 1;
                unsigned afr[2][4];
                #pragma unroll
                for (int mt = 0; mt < 2; mt++) {
                    int row = wm * 32 + mt * 16 + g;
                    #pragma unroll
                    for (int rg = 0; rg < 4; rg++) {
                        int r2 = row + (rg & 1) * 8;
                        int c  = kb + tg * 2 + (rg >> 1) * 8;
                        afr[mt][rg] = *(const unsigned*)&sY[as][r2][c];
                    }
                }
                #pragma unroll
                for (int nt = 0; nt < 4; nt++) {
                    int dd = wn * 32 + nt * 8 + g;
                    unsigned bfr[2];
                    #pragma unroll
                    for (int rg = 0; rg < 2; rg++) {
                        int k = kb + tg * 2 + rg * 8;
                        bfr[rg] = *(const unsigned*)&sWo[bs][dd][k];
                    }
                    #pragma unroll
                    for (int mt = 0; mt < 2; mt++)
                        mma_bf16(acc[mt][nt], afr[mt], bfr);
                }
            }
        }
        __syncthreads();
    }

    // write deterministic split-K partials (float2 stores)
    float* part = g_part + kp * (MM * DD);
    #pragma unroll
    for (int mt = 0; mt < 2; mt++) {
        #pragma unroll
        for (int nt = 0; nt < 4; nt++) {
            int mr0 = m0 + wm * 32 + mt * 16 + g;
            int dc0 = wn * 32 + nt * 8 + tg * 2;
            #pragma unroll
            for (int half = 0; half < 2; half++) {
                int mr = mr0 + half * 8;
                float2 v;
                v.x = acc[mt][nt][half * 2 + 0];
                v.y = acc[mt][nt][half * 2 + 1];
                *(float2*)&part[mr * DD + dc0] = v;
            }
        }
    }
}

// ---------------- 6) reduce split-K partials + bias ----------------
__global__ void reduce_out(const float* __restrict__ bout, float* __restrict__ out) {
    int i = blockIdx.x * blockDim.x + threadIdx.x;    // 524288 threads
    if (i < MM * DD) {
        const int MD = MM * DD;
        float v = bout[i & (DD - 1)];
        v += g_part[i] + g_part[MD + i] + g_part[2 * MD + i] + g_part[3 * MD + i];
        out[i] = v;
    }
}

// ---------------- launch ----------------
extern "C" void kernel_launch(void* const* d_in, const int* in_sizes, int n_in,
                              void* d_out, int out_size) {
    const float* x     = (const float*)d_in[0];
    const float* W_B   = (const float*)d_in[1];
    const float* b_B   = (const float*)d_in[2];
    const float* W_C   = (const float*)d_in[3];
    const float* b_C   = (const float*)d_in[4];
    const float* W_dt  = (const float*)d_in[5];
    const float* b_dt  = (const float*)d_in[6];
    const float* A_log = (const float*)d_in[7];
    const float* W_out = (const float*)d_in[8];
    const float* b_out = (const float*)d_in[9];
    float* out = (float*)d_out;

    split_kernel<<<6144, 256>>>(x, W_B, W_C, W_dt, W_out);
    gemm1_proj<<<dim3(32, 32), 256>>>(b_B, b_C, b_dt, A_log);
    scan_pass1<<<512, 256>>>();
    scan_combine<<<16, 256>>>();
    scan_pass2<<<512, 256>>>();
    gemm2_out<<<dim3(64, 4), 256>>>();
    reduce_out<<<2048, 256>>>(b_out, out);
}

// round 5
// speedup vs baseline: 1.5108x; 1.5108x over previous
#include <cuda_runtime.h>
#include <cuda_bf16.h>
#include <math.h>

// Problem constants
#define BB   2
#define SS   2048
#define DD   128
#define NN   2048
#define MM   (BB * SS)          // 4096 rows
#define NCH  32                 // scan chunks
#define LCH  64                 // steps per chunk (NCH*LCH == SS)

// ---------------- scratch (static device globals; no allocations) ----------------
__device__ __nv_bfloat16 g_xh[MM * DD], g_xl[MM * DD];           // split x
__device__ __nv_bfloat16 g_Wh[3 * NN * DD], g_Wl[3 * NN * DD];   // split [W_B; W_C; W_dt]
__device__ __nv_bfloat16 g_Woh[DD * NN], g_Wol[DD * NN];         // split W_out
__device__ float g_abar[MM * NN];                                // exp(dt*A)
__device__ float g_bbar[MM * NN];                                // dt*B_feat
__device__ float g_cf  [MM * NN];                                // C_feat
__device__ __nv_bfloat16 g_yh[MM * NN], g_yl[MM * NN];           // split y = c*h
__device__ float g_Aprod [BB * NCH * NN];
__device__ float g_Hend  [BB * NCH * NN];
__device__ float g_Hstart[BB * NCH * NN];
__device__ float g_part[4 * MM * DD];                            // split-K partials

// ---------------- helpers ----------------
__device__ __forceinline__ void bf16_split(float v, __nv_bfloat16& h, __nv_bfloat16& l) {
    h = __float2bfloat16(v);
    l = __float2bfloat16(v - __bfloat162float(h));
}

__device__ __forceinline__ void mma_bf16(float* c, const unsigned* a, const unsigned* b) {
    asm volatile(
        "mma.sync.aligned.m16n8k16.row.col.f32.bf16.bf16.f32 "
        "{%0,%1,%2,%3}, {%4,%5,%6,%7}, {%8,%9}, {%0,%1,%2,%3};\n"
        : "+f"(c[0]), "+f"(c[1]), "+f"(c[2]), "+f"(c[3])
        : "r"(a[0]), "r"(a[1]), "r"(a[2]), "r"(a[3]),
          "r"(b[0]), "r"(b[1]));
}

__device__ __forceinline__ void cp16(void* smem_dst, const void* gmem_src) {
    unsigned s = (unsigned)__cvta_generic_to_shared(smem_dst);
    asm volatile("cp.async.cg.shared.global [%0], [%1], 16;\n" :: "r"(s), "l"(gmem_src));
}
#define CP_COMMIT() asm volatile("cp.async.commit_group;\n" ::: "memory")
#define CP_WAIT1()  asm volatile("cp.async.wait_group 1;\n" ::: "memory")

// ---------------- 0) split inputs into bf16 hi/lo ----------------
__global__ void split_kernel(const float* __restrict__ x,
                             const float* __restrict__ WB,
                             const float* __restrict__ WC,
                             const float* __restrict__ Wdt,
                             const float* __restrict__ Wout) {
    const int XE  = MM * DD;        // 524288
    const int WE  = NN * DD;        // 262144 per matrix
    const int WOE = DD * NN;        // 262144
    int i = blockIdx.x * blockDim.x + threadIdx.x;
    if (i < XE) {
        bf16_split(x[i], g_xh[i], g_xl[i]);
    } else if (i < XE + 3 * WE) {
        int j = i - XE;
        const float* W = (j < WE) ? WB : ((j < 2 * WE) ? WC : Wdt);
        float v = W[j % WE];
        bf16_split(v, g_Wh[j], g_Wl[j]);
    } else if (i < XE + 3 * WE + WOE) {
        int j = i - XE - 3 * WE;
        bf16_split(Wout[j], g_Woh[j], g_Wol[j]);
    }
}

// ---------------- 1) fused projection GEMM + SSM featurizer epilogue ----------------
// Block tile: 128 (m) x 64 (n), K=128 in 4 chunks of 32, cp.async double-buffered.
// Dynamic smem layout: sX[2buf][2sel][128][40] then sW[2buf][3mat][2sel][64][40]
#define G1_SX_ELEMS (2*2*128*40)
#define G1_SW_ELEMS (2*3*2*64*40)
#define G1_SMEM ((G1_SX_ELEMS + G1_SW_ELEMS) * 2)

__global__ __launch_bounds__(256, 1)
void gemm1_proj(const float* __restrict__ bB, const float* __restrict__ bC,
                const float* __restrict__ bdt, const float* __restrict__ Alog) {
    extern __shared__ unsigned short smem_u16[];
    typedef unsigned short (*SXt)[2][128][40];
    typedef unsigned short (*SWt)[3][2][64][40];
    SXt sX = (SXt)smem_u16;
    SWt sW = (SWt)(smem_u16 + G1_SX_ELEMS);

    const int tid  = threadIdx.x;
    const int warp = tid >> 5, lane = tid & 31;
    const int wm = warp >> 1, wn = warp & 1;
    const int m0 = blockIdx.y * 128;
    const int n0 = blockIdx.x * 64;
    const int g  = lane >> 2, tg = lane & 3;

    float acc[3][2][4][4];
    #pragma unroll
    for (int a = 0; a < 3; a++)
        #pragma unroll
        for (int b = 0; b < 2; b++)
            #pragma unroll
            for (int c = 0; c < 4; c++)
                #pragma unroll
                for (int d = 0; d < 4; d++) acc[a][b][c][d] = 0.f;

    // async tile loader for k-chunk kc into buffer buf
    auto load_tiles = [&](int buf, int kc) {
        #pragma unroll
        for (int j = 0; j < 4; j++) {               // x: 1024 x 16B
            int i = tid + j * 256;
            int sel = i >> 9, r = (i >> 2) & 127, w = i & 3;
            const __nv_bfloat16* src = (sel ? g_xl : g_xh) + (m0 + r) * DD + kc * 32 + w * 8;
            cp16(&sX[buf][sel][r][w * 8], src);
        }
        #pragma unroll
        for (int j = 0; j < 6; j++) {               // W: 1536 x 16B
            int i = tid + j * 256;
            int mat = i >> 9, sel = (i >> 8) & 1, r = (i >> 2) & 63, w = i & 3;
            const __nv_bfloat16* src = (sel ? g_Wl : g_Wh) + (mat * NN + n0 + r) * DD + kc * 32 + w * 8;
            cp16(&sW[buf][mat][sel][r][w * 8], src);
        }
    };

    load_tiles(0, 0);
    CP_COMMIT();

    for (int kc = 0; kc < 4; kc++) {
        if (kc < 3) load_tiles((kc + 1) & 1, kc + 1);
        CP_COMMIT();                 // real group, or empty group on last iter
        CP_WAIT1();                  // forces chunk-kc group completion
        __syncthreads();
        const int buf = kc & 1;

        #pragma unroll
        for (int ks = 0; ks < 2; ks++) {
            const int kb = ks * 16;
            #pragma unroll
            for (int pass = 0; pass < 3; pass++) {
                const int as = pass >> 1;   // 0,0,1
                const int bs = pass & 1;    // 0,1,0
                unsigned afr[2][4];
                #pragma unroll
                for (int mt = 0; mt < 2; mt++) {
                    int row = wm * 32 + mt * 16 + g;
                    #pragma unroll
                    for (int rg = 0; rg < 4; rg++) {
                        int r2 = row + (rg & 1) * 8;
                        int c  = kb + tg * 2 + (rg >> 1) * 8;
                        afr[mt][rg] = *(const unsigned*)&sX[buf][as][r2][c];
                    }
                }
                #pragma unroll
                for (int nt = 0; nt < 4; nt++) {
                    int nn = wn * 32 + nt * 8 + g;
                    #pragma unroll
                    for (int mat = 0; mat < 3; mat++) {
                        unsigned bfr[2];
                        #pragma unroll
                        for (int rg = 0; rg < 2; rg++) {
                            int k = kb + tg * 2 + rg * 8;
                            bfr[rg] = *(const unsigned*)&sW[buf][mat][bs][nn][k];
                        }
                        #pragma unroll
                        for (int mt = 0; mt < 2; mt++)
                            mma_bf16(acc[mat][mt][nt], afr[mt], bfr);
                    }
                }
            }
        }
        __syncthreads();
    }

    // epilogue: SSM featurizer transforms, vectorized float2 stores
    #pragma unroll
    for (int mt = 0; mt < 2; mt++) {
        #pragma unroll
        for (int nt = 0; nt < 4; nt++) {
            int mrow0 = m0 + wm * 32 + mt * 16 + g;
            int ncol0 = n0 + wn * 32 + nt * 8 + tg * 2;
            #pragma unroll
            for (int half = 0; half < 2; half++) {
                int mr = mrow0 + half * 8;
                float2 oab, obb, ocf;
                #pragma unroll
                for (int col = 0; col < 2; col++) {
                    int rg = half * 2 + col;
                    int nc = ncol0 + col;
                    float vB = acc[0][mt][nt][rg] + bB[nc];
                    float vC = acc[1][mt][nt][rg] + bC[nc];
                    float t  = acc[2][mt][nt][rg] + bdt[nc];
                    float dtv = (t > 20.f) ? t : log1pf(__expf(t));
                    float A = -__expf(Alog[nc]);
                    float ab = __expf(dtv * A);
                    ((float*)&oab)[col] = ab;
                    ((float*)&obb)[col] = dtv * vB;
                    ((float*)&ocf)[col] = vC;
                }
                int idx = mr * NN + ncol0;
                *(float2*)&g_abar[idx] = oab;
                *(float2*)&g_bbar[idx] = obb;
                *(float2*)&g_cf[idx]   = ocf;
            }
        }
    }
}

// ---------------- 2) chunked scan pass 1 (float2 vectorized) ----------------
__global__ void scan_pass1() {
    int t  = blockIdx.x * blockDim.x + threadIdx.x;   // 65536 threads
    int n2 = (t & 1023) << 1;
    int ch = (t >> 10) & (NCH - 1);
    int b  = t >> 15;
    const float2* pa = (const float2*)(g_abar + (b * SS + ch * LCH) * NN + n2);
    const float2* pb = (const float2*)(g_bbar + (b * SS + ch * LCH) * NN + n2);
    float2 h = make_float2(0.f, 0.f);
    float2 p = make_float2(1.f, 1.f);
    #pragma unroll 8
    for (int s = 0; s < LCH; s++) {
        float2 a  = pa[s * (NN / 2)];
        float2 bb = pb[s * (NN / 2)];
        h.x = fmaf(a.x, h.x, bb.x);
        h.y = fmaf(a.y, h.y, bb.y);
        p.x *= a.x;
        p.y *= a.y;
    }
    int o = (b * NCH + ch) * NN + n2;
    *(float2*)&g_Aprod[o] = p;
    *(float2*)&g_Hend[o]  = h;
}

// ---------------- 3) chunk combine: warp-shuffle Kogge-Stone scan ----------------
// One warp per (b, n); lane = chunk index. (a,h) composes as h' = a*h_prev + h.
__global__ void scan_combine() {
    int t    = blockIdx.x * blockDim.x + threadIdx.x;   // 131072 threads = 4096 warps
    int lane = t & 31;
    int w    = t >> 5;
    int n    = w & (NN - 1);
    int b    = w >> 11;
    int idx  = (b * NCH + lane) * NN + n;
    float a = g_Aprod[idx];
    float h = g_Hend[idx];
    #pragma unroll
    for (int d = 1; d < 32; d <<= 1) {
        float al = __shfl_up_sync(0xFFFFFFFFu, a, d);
        float hl = __shfl_up_sync(0xFFFFFFFFu, h, d);
        if (lane >= d) {
            h = fmaf(a, hl, h);
            a *= al;
        }
    }
    float hex = __shfl_up_sync(0xFFFFFFFFu, h, 1);      // exclusive
    g_Hstart[idx] = (lane == 0) ? 0.f : hex;
}

// ---------------- 4) scan pass 2: replay with correct h0, emit y split ------------
__global__ void scan_pass2() {
    int t  = blockIdx.x * blockDim.x + threadIdx.x;     // 65536 threads
    int n2 = (t & 1023) << 1;
    int ch = (t >> 10) & (NCH - 1);
    int b  = t >> 15;
    int base = (b * SS + ch * LCH) * NN + n2;
    const float2* pa = (const float2*)(g_abar + base);
    const float2* pb = (const float2*)(g_bbar + base);
    const float2* pc = (const float2*)(g_cf   + base);
    __nv_bfloat162* yh = (__nv_bfloat162*)(g_yh + base);
    __nv_bfloat162* yl = (__nv_bfloat162*)(g_yl + base);
    float2 h = *(const float2*)&g_Hstart[(b * NCH + ch) * NN + n2];
    #pragma unroll 4
    for (int s = 0; s < LCH; s++) {
        float2 a  = pa[s * (NN / 2)];
        float2 bb = pb[s * (NN / 2)];
        float2 c  = pc[s * (NN / 2)];
        h.x = fmaf(a.x, h.x, bb.x);
        h.y = fmaf(a.y, h.y, bb.y);
        float yx = c.x * h.x, yy = c.y * h.y;
        __nv_bfloat16 hx = __float2bfloat16(yx);
        __nv_bfloat16 hy = __float2bfloat16(yy);
        float lx = yx - __bfloat162float(hx);
        float ly = yy - __bfloat162float(hy);
        yh[s * (NN / 2)] = __halves2bfloat162(hx, hy);
        yl[s * (NN / 2)] = __halves2bfloat162(__float2bfloat16(lx), __float2bfloat16(ly));
    }
}

// ---------------- 5) output projection GEMM (split-K=4, cp.async pipelined) -------
// out[m,d] = sum_n y[m,n] * W_out[d,n].  Block: 64 (m) x 128 (d), 512 K per block.
#define G2_SY_ELEMS (2*2*64*40)
#define G2_SW_ELEMS (2*2*128*40)
#define G2_SMEM ((G2_SY_ELEMS + G2_SW_ELEMS) * 2)

__global__ __launch_bounds__(256)
void gemm2_out() {
    extern __shared__ unsigned short smem2_u16[];
    typedef unsigned short (*SYt)[2][64][40];
    typedef unsigned short (*SWot)[2][128][40];
    SYt  sY  = (SYt)smem2_u16;
    SWot sWo = (SWot)(smem2_u16 + G2_SY_ELEMS);

    const int tid  = threadIdx.x;
    const int warp = tid >> 5, lane = tid & 31;
    const int wm = warp >> 2, wn = warp & 3;
    const int m0 = blockIdx.x * 64;
    const int kp = blockIdx.y;              // 0..3
    const int g  = lane >> 2, tg = lane & 3;

    float acc[2][4][4];
    #pragma unroll
    for (int a = 0; a < 2; a++)
        #pragma unroll
        for (int b = 0; b < 4; b++)
            #pragma unroll
            for (int c = 0; c < 4; c++) acc[a][b][c] = 0.f;

    auto load_tiles = [&](int buf, int kc) {
        const int kbase = kp * 512 + kc * 32;
        #pragma unroll
        for (int j = 0; j < 2; j++) {               // y: 512 x 16B
            int i = tid + j * 256;
            int sel = i >> 8, r = (i >> 2) & 63, w = i & 3;
            const __nv_bfloat16* src = (sel ? g_yl : g_yh) + (m0 + r) * NN + kbase + w * 8;
            cp16(&sY[buf][sel][r][w * 8], src);
        }
        #pragma unroll
        for (int j = 0; j < 4; j++) {               // W_out: 1024 x 16B
            int i = tid + j * 256;
            int sel = i >> 9, r = (i >> 2) & 127, w = i & 3;
            const __nv_bfloat16* src = (sel ? g_Wol : g_Woh) + r * NN + kbase + w * 8;
            cp16(&sWo[buf][sel][r][w * 8], src);
        }
    };

    load_tiles(0, 0);
    CP_COMMIT();

    for (int kc = 0; kc < 16; kc++) {
        if (kc < 15) load_tiles((kc + 1) & 1, kc + 1);
        CP_COMMIT();
        CP_WAIT1();
        __syncthreads();
        const int buf = kc & 1;

        #pragma unroll
        for (int ks = 0; ks < 2; ks++) {
            const int kb = ks * 16;
            #pragma unroll
            for (int pass = 0; pass < 3; pass++) {
                const int as = pass >> 1;
                const int bs = pass & 1;
                unsigned afr[2][4];
                #pragma unroll
                for (int mt = 0; mt < 2; mt++) {
                    int row = wm * 32 + mt * 16 + g;
                    #pragma unroll
                    for (int rg = 0; rg < 4; rg++) {
                        int r2 = row + (rg & 1) * 8;
                        int c  = kb + tg * 2 + (rg >> 1) * 8;
                        afr[mt][rg] = *(const unsigned*)&sY[buf][as][r2][c];
                    }
                }
                #pragma unroll
                for (int nt = 0; nt < 4; nt++) {
                    int dd = wn * 32 + nt * 8 + g;
                    unsigned bfr[2];
                    #pragma unroll
                    for (int rg = 0; rg < 2; rg++) {
                        int k = kb + tg * 2 + rg * 8;
                        bfr[rg] = *(const unsigned*)&sWo[buf][bs][dd][k];
                    }
                    #pragma unroll
                    for (int mt = 0; mt < 2; mt++)
                        mma_bf16(acc[mt][nt], afr[mt], bfr);
                }
            }
        }
        __syncthreads();
    }

    // write deterministic split-K partials (float2 stores)
    float* part = g_part + kp * (MM * DD);
    #pragma unroll
    for (int mt = 0; mt < 2; mt++) {
        #pragma unroll
        for (int nt = 0; nt < 4; nt++) {
            int mr0 = m0 + wm * 32 + mt * 16 + g;
            int dc0 = wn * 32 + nt * 8 + tg * 2;
            #pragma unroll
            for (int half = 0; half < 2; half++) {
                int mr = mr0 + half * 8;
                float2 v;
                v.x = acc[mt][nt][half * 2 + 0];
                v.y = acc[mt][nt][half * 2 + 1];
                *(float2*)&part[mr * DD + dc0] = v;
            }
        }
    }
}

// ---------------- 6) reduce split-K partials + bias (float4) ----------------
__global__ void reduce_out(const float* __restrict__ bout, float* __restrict__ out) {
    int i = blockIdx.x * blockDim.x + threadIdx.x;    // 131072 threads
    if (i < MM * DD / 4) {
        const int MD = MM * DD;
        float4 v = *(const float4*)&bout[(i * 4) & (DD - 1)];
        float4 p0 = *(const float4*)&g_part[i * 4];
        float4 p1 = *(const float4*)&g_part[MD + i * 4];
        float4 p2 = *(const float4*)&g_part[2 * MD + i * 4];
        float4 p3 = *(const float4*)&g_part[3 * MD + i * 4];
        v.x += p0.x + p1.x + p2.x + p3.x;
        v.y += p0.y + p1.y + p2.y + p3.y;
        v.z += p0.z + p1.z + p2.z + p3.z;
        v.w += p0.w + p1.w + p2.w + p3.w;
        *(float4*)&out[i * 4] = v;
    }
}

// ---------------- launch ----------------
extern "C" void kernel_launch(void* const* d_in, const int* in_sizes, int n_in,
                              void* d_out, int out_size) {
    const float* x     = (const float*)d_in[0];
    const float* W_B   = (const float*)d_in[1];
    const float* b_B   = (const float*)d_in[2];
    const float* W_C   = (const float*)d_in[3];
    const float* b_C   = (const float*)d_in[4];
    const float* W_dt  = (const float*)d_in[5];
    const float* b_dt  = (const float*)d_in[6];
    const float* A_log = (const float*)d_in[7];
    const float* W_out = (const float*)d_in[8];
    const float* b_out = (const float*)d_in[9];
    float* out = (float*)d_out;

    cudaFuncSetAttribute(gemm1_proj, cudaFuncAttributeMaxDynamicSharedMemorySize, G1_SMEM);
    cudaFuncSetAttribute(gemm2_out,  cudaFuncAttributeMaxDynamicSharedMemorySize, G2_SMEM);

    split_kernel<<<6144, 256>>>(x, W_B, W_C, W_dt, W_out);
    gemm1_proj<<<dim3(32, 32), 256, G1_SMEM>>>(b_B, b_C, b_dt, A_log);
    scan_pass1<<<256, 256>>>();
    scan_combine<<<512, 256>>>();
    scan_pass2<<<256, 256>>>();
    gemm2_out<<<dim3(64, 4), 256, G2_SMEM>>>();
    reduce_out<<<512, 256>>>(b_out, out);
}